// round 14
// baseline (speedup 1.0000x reference)
#include <cuda_runtime.h>
#include <math.h>

#define TT 2048
#define CC 2048
#define NH 16
#define HD 128
#define QDIM 2048
#define KVDIM 512

// scratch (__device__ globals; allocation-free rule)
__device__ float g_q[TT * QDIM];
__device__ float g_k[TT * KVDIM];
__device__ float g_v[TT * KVDIM];
__device__ float g_y[TT * QDIM];
__device__ float g_rx[TT * CC];          // x, tf32-rounded
__device__ float g_wqT[QDIM * CC];       // Wq^T [n][k], rounded
__device__ float g_wkT[KVDIM * CC];      // Wk^T
__device__ float g_wvT[KVDIM * CC];      // Wv^T
__device__ float g_woT[CC * QDIM];       // Wo^T
__device__ float g_vT[KVDIM * TT];       // V^T [kv*HD+d][t], rounded
__device__ float g_rcs[TT * 64];         // rope cos table
__device__ float g_rsn[TT * 64];         // rope sin table

// ---------------------------------------------------------------------------
// helpers
// ---------------------------------------------------------------------------
__device__ __forceinline__ unsigned f2tf(float f) {
    unsigned u;
    asm("cvt.rna.tf32.f32 %0, %1;" : "=r"(u) : "f"(f));
    return u;
}
__device__ __forceinline__ float4 cvt4(float4 v) {
    float4 r;
    r.x = __uint_as_float(f2tf(v.x));
    r.y = __uint_as_float(f2tf(v.y));
    r.z = __uint_as_float(f2tf(v.z));
    r.w = __uint_as_float(f2tf(v.w));
    return r;
}
__device__ __forceinline__ void mma_tf32(float* c, const unsigned* a, const unsigned* b) {
    asm volatile(
        "mma.sync.aligned.m16n8k8.row.col.f32.tf32.tf32.f32 "
        "{%0,%1,%2,%3}, {%4,%5,%6,%7}, {%8,%9}, {%0,%1,%2,%3};"
        : "+f"(c[0]), "+f"(c[1]), "+f"(c[2]), "+f"(c[3])
        : "r"(a[0]), "r"(a[1]), "r"(a[2]), "r"(a[3]), "r"(b[0]), "r"(b[1]));
}
__device__ __forceinline__ void ldsm4(unsigned& r0, unsigned& r1, unsigned& r2,
                                      unsigned& r3, unsigned saddr) {
    asm volatile("ldmatrix.sync.aligned.m8n8.x4.shared.b16 {%0,%1,%2,%3}, [%4];"
                 : "=r"(r0), "=r"(r1), "=r"(r2), "=r"(r3) : "r"(saddr));
}
__device__ __forceinline__ void cp16(float* dst, const float* src) {
    unsigned d = (unsigned)__cvta_generic_to_shared(dst);
    asm volatile("cp.async.cg.shared.global [%0], [%1], 16;\n" ::"r"(d), "l"(src));
}
#define CP_COMMIT() asm volatile("cp.async.commit_group;\n")
#define CP_WAIT0()  asm volatile("cp.async.wait_group 0;\n")
#define CP_WAIT1()  asm volatile("cp.async.wait_group 1;\n")

// ---------------------------------------------------------------------------
// pre-pass kernels
// ---------------------------------------------------------------------------
__global__ void round_copy_kernel(const float* __restrict__ src, float* __restrict__ dst)
{
    int i = blockIdx.x * 256 + threadIdx.x;
    *(float4*)&dst[i * 4] = cvt4(*(const float4*)&src[i * 4]);
}

// rope cos/sin table: fully parallel dp sincos.
__global__ void rope_table_kernel(const int* __restrict__ pos_ids)
{
    int i = blockIdx.x * 256 + threadIdx.x;
    int tpos = i >> 6, p = i & 63;
    double invf = exp(-0.14391156831212788 * (double)p);
    double fr = (double)pos_ids[tpos] * invf;
    double s, c;
    sincos(fr, &s, &c);
    g_rcs[i] = (float)c;
    g_rsn[i] = (float)s;
}

__device__ __forceinline__ void transpose_tile(
    const float* __restrict__ src, float* __restrict__ dst, int R, int C,
    int c0, int r0, float (*tile)[33])
{
#pragma unroll
    for (int i = threadIdx.y; i < 32; i += 8)
        tile[i][threadIdx.x] = src[(size_t)(r0 + i) * C + c0 + threadIdx.x];
    __syncthreads();
#pragma unroll
    for (int i = threadIdx.y; i < 32; i += 8)
        dst[(size_t)(c0 + i) * R + r0 + threadIdx.x] =
            __uint_as_float(f2tf(tile[threadIdx.x][i]));
}

// All 4 weight transposes in one launch. grid (64, 64, 4).
__global__ void prep_weights_kernel(const float* __restrict__ Wq, const float* __restrict__ Wk,
                                    const float* __restrict__ Wv, const float* __restrict__ Wo)
{
    __shared__ float tile[32][33];
    int z = blockIdx.z;
    const float* src; float* dst; int R, C;
    if (z == 0)      { src = Wq; dst = g_wqT; R = CC;   C = QDIM; }
    else if (z == 1) { src = Wk; dst = g_wkT; R = CC;   C = KVDIM; }
    else if (z == 2) { src = Wv; dst = g_wvT; R = CC;   C = KVDIM; }
    else             { src = Wo; dst = g_woT; R = QDIM; C = CC; }
    int c0 = blockIdx.x * 32, r0 = blockIdx.y * 32;
    if (c0 >= C || r0 >= R) return;
    transpose_tile(src, dst, R, C, c0, r0, tile);
}

__global__ void transpose_round_kernel(const float* __restrict__ src, float* __restrict__ dst,
                                       int R, int C)
{
    __shared__ float tile[32][33];
    transpose_tile(src, dst, R, C, blockIdx.x * 32, blockIdx.y * 32, tile);
}

// ---------------------------------------------------------------------------
// tf32 GEMM: C[M,N] = A[m][k] @ Bt[n][k]^T, pre-rounded tf32 operands.
// 128x256 block tile, BK=32, 8 warps (warp tile 32x128), ldmatrix,
// 3-stage cp.async, 1 CTA/SM.
// ---------------------------------------------------------------------------
#define GST 36
#define A_SZ (128 * GST)
#define B_SZ (256 * GST)
#define STAGE_F (A_SZ + B_SZ)
#define GEMM_SMEM (3 * STAGE_F * 4)      // 165.9 KB

__device__ __forceinline__ void gemm_wide(
    const float* __restrict__ A, const float* __restrict__ Bt, float* __restrict__ Cm,
    int N, int K, int bm, int bn, float* sm)
{
    int tid = threadIdx.x;
    int lane = tid & 31, wid = tid >> 5;
    int g = lane >> 2, t = lane & 3;
    int wm = wid & 3, wn = wid >> 2;          // warp tile: rows 32*wm, cols 128*wn
    int sel = lane >> 3, r = lane & 7;

    unsigned sbase = (unsigned)__cvta_generic_to_shared(sm);
    unsigned aoff[2], boff[8];
#pragma unroll
    for (int i = 0; i < 2; i++)
        aoff[i] = ((32 * wm + 16 * i + (sel & 1) * 8 + r) * GST + (sel >> 1) * 4) * 4;
#pragma unroll
    for (int jp = 0; jp < 8; jp++)
        boff[jp] = (A_SZ + (128 * wn + 16 * jp + (sel >> 1) * 8 + r) * GST
                    + (sel & 1) * 4) * 4;

    float acc[2][16][4];
#pragma unroll
    for (int i = 0; i < 2; i++)
#pragma unroll
        for (int j = 0; j < 16; j++)
#pragma unroll
            for (int c = 0; c < 4; c++) acc[i][j][c] = 0.f;

    int m8 = tid >> 3, kc = (tid & 7) * 4;
    const float* Ab = A + (size_t)(bm + m8) * K + kc;
    const float* Bb = Bt + (size_t)(bn + m8) * K + kc;
    int nt = K >> 5;

    // prologue: stages 0,1
#pragma unroll
    for (int s = 0; s < 2; s++) {
        float* Sa = sm + s * STAGE_F;
        float* Sb = Sa + A_SZ;
#pragma unroll
        for (int v = 0; v < 4; v++)
            cp16(Sa + (m8 + 32 * v) * GST + kc, Ab + (size_t)(32 * v) * K + s * 32);
#pragma unroll
        for (int v = 0; v < 8; v++)
            cp16(Sb + (m8 + 32 * v) * GST + kc, Bb + (size_t)(32 * v) * K + s * 32);
        CP_COMMIT();
    }

    for (int kt = 0; kt < nt; kt++) {
        CP_WAIT1();
        __syncthreads();

        if (kt + 2 < nt) {
            int s = (kt + 2) % 3;
            float* Sa = sm + s * STAGE_F;
            float* Sb = Sa + A_SZ;
            int ko = (kt + 2) * 32;
#pragma unroll
            for (int v = 0; v < 4; v++)
                cp16(Sa + (m8 + 32 * v) * GST + kc, Ab + (size_t)(32 * v) * K + ko);
#pragma unroll
            for (int v = 0; v < 8; v++)
                cp16(Sb + (m8 + 32 * v) * GST + kc, Bb + (size_t)(32 * v) * K + ko);
        }
        CP_COMMIT();

        unsigned st = sbase + (kt % 3) * (STAGE_F * 4);
#pragma unroll
        for (int ks = 0; ks < 4; ks++) {
            unsigned kb = ks * 32;
            unsigned a[2][4];
#pragma unroll
            for (int i = 0; i < 2; i++)
                ldsm4(a[i][0], a[i][1], a[i][2], a[i][3], st + aoff[i] + kb);
#pragma unroll
            for (int jp = 0; jp < 8; jp++) {
                unsigned b0, b1, b2, b3;
                ldsm4(b0, b1, b2, b3, st + boff[jp] + kb);
                unsigned bl[2] = {b0, b1}, bh[2] = {b2, b3};
#pragma unroll
                for (int i = 0; i < 2; i++) {
                    mma_tf32(acc[i][2 * jp], a[i], bl);
                    mma_tf32(acc[i][2 * jp + 1], a[i], bh);
                }
            }
        }
    }

#pragma unroll
    for (int i = 0; i < 2; i++) {
        int row = bm + 32 * wm + 16 * i + g;
#pragma unroll
        for (int j = 0; j < 16; j++) {
            int col = bn + 128 * wn + 8 * j + 2 * t;
            *(float2*)&Cm[(size_t)row * N + col]       = make_float2(acc[i][j][0], acc[i][j][1]);
            *(float2*)&Cm[(size_t)(row + 8) * N + col] = make_float2(acc[i][j][2], acc[i][j][3]);
        }
    }
}

// qkv: grid (12, 16). x: 0..7 Q (256-col blocks), 8..9 K, 10..11 V.
__global__ __launch_bounds__(256, 1) void qkv_gemm_kernel()
{
    extern __shared__ float sm[];
    int bnb = blockIdx.x;
    int bm  = blockIdx.y * 128;
    const float* B; float* O; int N; int bn;
    if (bnb < 8)       { B = g_wqT; O = g_q; N = QDIM;  bn = bnb * 256; }
    else if (bnb < 10) { B = g_wkT; O = g_k; N = KVDIM; bn = (bnb - 8) * 256; }
    else               { B = g_wvT; O = g_v; N = KVDIM; bn = (bnb - 10) * 256; }
    gemm_wide(g_rx, B, O, N, CC, bm, bn, sm);
}

__global__ __launch_bounds__(256, 1) void out_gemm_kernel(float* __restrict__ out)
{
    extern __shared__ float sm[];
    gemm_wide(g_y, g_woT, out, CC, QDIM, blockIdx.y * 128, blockIdx.x * 256, sm);
}

// ---------------------------------------------------------------------------
// RoPE: reads precomputed cos/sin table; q plain fp32, k tf32-rounded.
// ---------------------------------------------------------------------------
__global__ void rope_kernel()
{
    __shared__ float cs[64], sn[64];
    int t = blockIdx.x;
    if (threadIdx.x < 64) {
        cs[threadIdx.x] = g_rcs[t * 64 + threadIdx.x];
        sn[threadIdx.x] = g_rsn[t * 64 + threadIdx.x];
    }
    __syncthreads();
    for (int w = threadIdx.x; w < 20 * 64; w += blockDim.x) {
        int hs = w >> 6, p = w & 63;
        float cf = cs[p], sf = sn[p];
        if (hs < NH) {
            float* base = g_q + (size_t)t * QDIM + hs * HD;
            float a = base[p], b = base[p + 64];
            base[p]      = a * cf - b * sf;
            base[p + 64] = b * cf + a * sf;
        } else {
            float* base = g_k + (size_t)t * KVDIM + (hs - NH) * HD;
            float a = base[p], b = base[p + 64];
            base[p]      = __uint_as_float(f2tf(a * cf - b * sf));
            base[p + 64] = __uint_as_float(f2tf(b * cf + a * sf));
        }
    }
}

// ---------------------------------------------------------------------------
// Flash attention: warp tile 16 rows x 64 keys, ldmatrix fragments,
// fixed-max softmax, deferred l-reduce. V from g_vT [d][t].
// ---------------------------------------------------------------------------
#define QS_ST 132
#define KS_ST 132
#define VS_ST 68
#define PS_ST 68
#define VBUF  (128 * VS_ST)
#define ATTN_SMEM ((128 * QS_ST + 64 * KS_ST + 2 * VBUF + 128 * PS_ST) * 4)

__global__ __launch_bounds__(256, 1) void attn_kernel()
{
    extern __shared__ float sh[];
    float* Qs = sh;                      // [128][132] tf32 bits, pre-scaled
    float* Ks = Qs + 128 * QS_ST;        // [64 key][132] tf32 bits
    float* Vb = Ks + 64 * KS_ST;         // 2 x [128 d][68 key] tf32 bits
    float* Ps = Vb + 2 * VBUF;           // [128][68] tf32 bits
    unsigned* Pu = (unsigned*)Ps;

    int qb = 15 - blockIdx.x;
    int h  = blockIdx.y;
    int i0 = qb * 128;
    int kvh = h >> 2;
    int tid = threadIdx.x;
    int lane = tid & 31, wid = tid >> 5;
    int g = lane >> 2, t = lane & 3;
    int sel = lane >> 3, r = lane & 7;
    const float SCALE = 0.08838834764831845f;

    unsigned q_u  = (unsigned)__cvta_generic_to_shared(Qs);
    unsigned k_u  = (unsigned)__cvta_generic_to_shared(Ks);
    unsigned v_u  = (unsigned)__cvta_generic_to_shared(Vb);
    unsigned p_u  = (unsigned)__cvta_generic_to_shared(Ps);
    unsigned qa_off = ((16 * wid + (sel & 1) * 8 + r) * QS_ST + (sel >> 1) * 4) * 4;
    unsigned pa_off = ((16 * wid + (sel & 1) * 8 + r) * PS_ST + (sel >> 1) * 4) * 4;
    unsigned kb_off[4], vb_off[8];
#pragma unroll
    for (int jp = 0; jp < 4; jp++)
        kb_off[jp] = ((16 * jp + (sel >> 1) * 8 + r) * KS_ST + (sel & 1) * 4) * 4;
#pragma unroll
    for (int jp = 0; jp < 8; jp++)
        vb_off[jp] = ((16 * jp + (sel >> 1) * 8 + r) * VS_ST + (sel & 1) * 4) * 4;

    // prefetch K0 and V0
    {
        const float* kp = g_k + kvh * HD;
#pragma unroll
        for (int it = 0; it < 8; it++) {
            int c = it * 256 + tid;
            int row = c >> 5, c4 = (c & 31) * 4;
            cp16(Ks + row * KS_ST + c4, kp + (size_t)row * KVDIM + c4);
        }
        const float* vp = g_vT + (size_t)kvh * HD * TT;
#pragma unroll
        for (int it = 0; it < 8; it++) {
            int c = it * 256 + tid;
            int d = c >> 4, ck = (c & 15) * 4;
            cp16(Vb + d * VS_ST + ck, vp + (size_t)d * TT + ck);
        }
    }
    CP_COMMIT();

    // load Q (scaled + tf32)
#pragma unroll
    for (int v = 0; v < 16; v++) {
        int row = 8 * v + wid;
        float4 q = *(const float4*)&g_q[(size_t)(i0 + row) * QDIM + h * HD + lane * 4];
        q.x *= SCALE; q.y *= SCALE; q.z *= SCALE; q.w *= SCALE;
        *(float4*)&Qs[row * QS_ST + lane * 4] = cvt4(q);
    }

    float l0 = 0.f, l1 = 0.f;
    float oacc[16][4];
#pragma unroll
    for (int j = 0; j < 16; j++)
#pragma unroll
        for (int c = 0; c < 4; c++) oacc[j][c] = 0.f;

    int prow = (16 * wid + g) * PS_ST;
    int nkb = (i0 + 128) >> 6;
    for (int kb = 0; kb < nkb; kb++) {
        int cur = kb & 1;
        unsigned vcur_u = v_u + cur * (VBUF * 4);

        CP_WAIT0();
        __syncthreads();                  // K(kb), V(kb) resident

        if (kb + 1 < nkb) {               // prefetch V(kb+1)
            const float* vpn = g_vT + (size_t)kvh * HD * TT + (kb + 1) * 64;
            float* Vn = Vb + (1 - cur) * VBUF;
#pragma unroll
            for (int it = 0; it < 8; it++) {
                int c = it * 256 + tid;
                int d = c >> 4, ck = (c & 15) * 4;
                cp16(Vn + d * VS_ST + ck, vpn + (size_t)d * TT + ck);
            }
            CP_COMMIT();
        }

        // ---- S = Q @ K^T ----
        float sacc[8][4];
#pragma unroll
        for (int j = 0; j < 8; j++)
#pragma unroll
            for (int c = 0; c < 4; c++) sacc[j][c] = 0.f;

#pragma unroll
        for (int ks = 0; ks < 16; ks++) {
            unsigned kbb = ks * 32;
            unsigned a[4];
            ldsm4(a[0], a[1], a[2], a[3], q_u + qa_off + kbb);
#pragma unroll
            for (int jp = 0; jp < 4; jp++) {
                unsigned b0, b1, b2, b3;
                ldsm4(b0, b1, b2, b3, k_u + kb_off[jp] + kbb);
                unsigned bl[2] = {b0, b1}, bh[2] = {b2, b3};
                mma_tf32(sacc[2 * jp], a, bl);
                mma_tf32(sacc[2 * jp + 1], a, bh);
            }
        }

        __syncthreads();                  // all warps done reading Ks

        if (kb + 1 < nkb) {               // refill K(kb+1); hides under softmax+PV
            const float* kpn = g_k + (size_t)(kb + 1) * 64 * KVDIM + kvh * HD;
#pragma unroll
            for (int it = 0; it < 8; it++) {
                int c = it * 256 + tid;
                int row = c >> 5, c4 = (c & 31) * 4;
                cp16(Ks + row * KS_ST + c4, kpn + (size_t)row * KVDIM + c4);
            }
            CP_COMMIT();
        }

        int j0 = kb * 64;
        if (j0 + 63 > i0) {               // diagonal tile mask (expf(-1e30) == 0)
            int r0 = i0 + 16 * wid + g;
            int r1 = r0 + 8;
#pragma unroll
            for (int j = 0; j < 8; j++) {
                int c = j0 + 8 * j + 2 * t;
                if (c > r0)     sacc[j][0] = -1e30f;
                if (c + 1 > r0) sacc[j][1] = -1e30f;
                if (c > r1)     sacc[j][2] = -1e30f;
                if (c + 1 > r1) sacc[j][3] = -1e30f;
            }
        }

        // exp + per-lane partial sums + write P
#pragma unroll
        for (int j = 0; j < 8; j++) {
            float e0 = __expf(sacc[j][0]);
            float e1 = __expf(sacc[j][1]);
            float e2 = __expf(sacc[j][2]);
            float e3 = __expf(sacc[j][3]);
            l0 += e0 + e1;
            l1 += e2 + e3;
            int pc = 8 * j + 2 * t;
            Pu[prow + pc]                 = f2tf(e0);
            Pu[prow + pc + 1]             = f2tf(e1);
            Pu[prow + 8 * PS_ST + pc]     = f2tf(e2);
            Pu[prow + 8 * PS_ST + pc + 1] = f2tf(e3);
        }
        __syncwarp();

        // ---- O += P @ V ----
#pragma unroll
        for (int ks = 0; ks < 8; ks++) {
            unsigned kbb = ks * 32;
            unsigned a[4];
            ldsm4(a[0], a[1], a[2], a[3], p_u + pa_off + kbb);
#pragma unroll
            for (int jp = 0; jp < 8; jp++) {
                unsigned b0, b1, b2, b3;
                ldsm4(b0, b1, b2, b3, vcur_u + vb_off[jp] + kbb);
                unsigned bl[2] = {b0, b1}, bh[2] = {b2, b3};
                mma_tf32(oacc[2 * jp], a, bl);
                mma_tf32(oacc[2 * jp + 1], a, bh);
            }
        }
    }

    // epilogue: reduce l once, normalize, round tf32
    l0 += __shfl_xor_sync(0xffffffffu, l0, 1);
    l0 += __shfl_xor_sync(0xffffffffu, l0, 2);
    l1 += __shfl_xor_sync(0xffffffffu, l1, 1);
    l1 += __shfl_xor_sync(0xffffffffu, l1, 2);
    float inv0 = 1.f / l0, inv1 = 1.f / l1;
    int row = i0 + 16 * wid + g;
#pragma unroll
    for (int j = 0; j < 16; j++) {
        int col = h * HD + 8 * j + 2 * t;
        float2 c0 = make_float2(__uint_as_float(f2tf(oacc[j][0] * inv0)),
                                __uint_as_float(f2tf(oacc[j][1] * inv0)));
        float2 c1 = make_float2(__uint_as_float(f2tf(oacc[j][2] * inv1)),
                                __uint_as_float(f2tf(oacc[j][3] * inv1)));
        *(float2*)&g_y[(size_t)row * QDIM + col]       = c0;
        *(float2*)&g_y[(size_t)(row + 8) * QDIM + col] = c1;
    }
}

// ---------------------------------------------------------------------------
extern "C" void kernel_launch(void* const* d_in, const int* in_sizes, int n_in,
                              void* d_out, int out_size)
{
    (void)in_sizes; (void)n_in; (void)out_size;
    const float* x  = (const float*)d_in[0];
    const float* Wq = (const float*)d_in[1];
    const float* Wk = (const float*)d_in[2];
    const float* Wv = (const float*)d_in[3];
    const float* Wo = (const float*)d_in[4];
    const int*  pos = (const int*)d_in[5];
    float* out = (float*)d_out;

    cudaFuncSetAttribute(attn_kernel,
                         cudaFuncAttributeMaxDynamicSharedMemorySize, ATTN_SMEM);
    cudaFuncSetAttribute(qkv_gemm_kernel,
                         cudaFuncAttributeMaxDynamicSharedMemorySize, GEMM_SMEM);
    cudaFuncSetAttribute(out_gemm_kernel,
                         cudaFuncAttributeMaxDynamicSharedMemorySize, GEMM_SMEM);

    float* rx = nullptr; float* gv = nullptr; float* gvT = nullptr;
    cudaGetSymbolAddress((void**)&rx,  g_rx);
    cudaGetSymbolAddress((void**)&gv,  g_v);
    cudaGetSymbolAddress((void**)&gvT, g_vT);

    round_copy_kernel<<<TT * CC / 1024, 256>>>(x, rx);
    rope_table_kernel<<<TT * 64 / 256, 256>>>(pos);
    prep_weights_kernel<<<dim3(64, 64, 4), dim3(32, 8)>>>(Wq, Wk, Wv, Wo);

    qkv_gemm_kernel<<<dim3(12, 16), 256, GEMM_SMEM>>>();
    rope_kernel<<<TT, 256>>>();
    transpose_round_kernel<<<dim3(KVDIM / 32, TT / 32), dim3(32, 8)>>>(gv, gvT, TT, KVDIM);
    attn_kernel<<<dim3(16, NH), 256, ATTN_SMEM>>>();
    out_gemm_kernel<<<dim3(8, 16), 256, GEMM_SMEM>>>(out);
}

// round 17
// speedup vs baseline: 1.0009x; 1.0009x over previous
#include <cuda_runtime.h>
#include <math.h>

#define TT 2048
#define CC 2048
#define NH 16
#define HD 128
#define QDIM 2048
#define KVDIM 512

// scratch (__device__ globals; allocation-free rule)
__device__ float g_q[TT * QDIM];
__device__ float g_k[TT * KVDIM];
__device__ float g_v[TT * KVDIM];
__device__ float g_y[TT * QDIM];
__device__ float g_rx[TT * CC];          // x, tf32-rounded
__device__ float g_wqT[QDIM * CC];       // Wq^T [n][k], rounded
__device__ float g_wkT[KVDIM * CC];      // Wk^T
__device__ float g_wvT[KVDIM * CC];      // Wv^T
__device__ float g_woT[CC * QDIM];       // Wo^T
__device__ float g_vT[KVDIM * TT];       // V^T [kv*HD+d][t], rounded
__device__ float g_rcs[TT * 64];         // rope cos table
__device__ float g_rsn[TT * 64];         // rope sin table

// ---------------------------------------------------------------------------
// helpers
// ---------------------------------------------------------------------------
__device__ __forceinline__ unsigned f2tf(float f) {
    unsigned u;
    asm("cvt.rna.tf32.f32 %0, %1;" : "=r"(u) : "f"(f));
    return u;
}
__device__ __forceinline__ float4 cvt4(float4 v) {
    float4 r;
    r.x = __uint_as_float(f2tf(v.x));
    r.y = __uint_as_float(f2tf(v.y));
    r.z = __uint_as_float(f2tf(v.z));
    r.w = __uint_as_float(f2tf(v.w));
    return r;
}
__device__ __forceinline__ void mma_tf32(float* c, const unsigned* a, const unsigned* b) {
    asm volatile(
        "mma.sync.aligned.m16n8k8.row.col.f32.tf32.tf32.f32 "
        "{%0,%1,%2,%3}, {%4,%5,%6,%7}, {%8,%9}, {%0,%1,%2,%3};"
        : "+f"(c[0]), "+f"(c[1]), "+f"(c[2]), "+f"(c[3])
        : "r"(a[0]), "r"(a[1]), "r"(a[2]), "r"(a[3]), "r"(b[0]), "r"(b[1]));
}
__device__ __forceinline__ void ldsm4(unsigned& r0, unsigned& r1, unsigned& r2,
                                      unsigned& r3, unsigned saddr) {
    asm volatile("ldmatrix.sync.aligned.m8n8.x4.shared.b16 {%0,%1,%2,%3}, [%4];"
                 : "=r"(r0), "=r"(r1), "=r"(r2), "=r"(r3) : "r"(saddr));
}
__device__ __forceinline__ void cp16(float* dst, const float* src) {
    unsigned d = (unsigned)__cvta_generic_to_shared(dst);
    asm volatile("cp.async.cg.shared.global [%0], [%1], 16;\n" ::"r"(d), "l"(src));
}
#define CP_COMMIT() asm volatile("cp.async.commit_group;\n")
#define CP_WAIT0()  asm volatile("cp.async.wait_group 0;\n")
#define CP_WAIT1()  asm volatile("cp.async.wait_group 1;\n")

// ---------------------------------------------------------------------------
// pre-pass kernels
// ---------------------------------------------------------------------------
__global__ void round_copy_kernel(const float* __restrict__ src, float* __restrict__ dst)
{
    int i = blockIdx.x * 256 + threadIdx.x;
    *(float4*)&dst[i * 4] = cvt4(*(const float4*)&src[i * 4]);
}

// rope cos/sin table: fully parallel dp sincos.
__global__ void rope_table_kernel(const int* __restrict__ pos_ids)
{
    int i = blockIdx.x * 256 + threadIdx.x;
    int tpos = i >> 6, p = i & 63;
    double invf = exp(-0.14391156831212788 * (double)p);
    double fr = (double)pos_ids[tpos] * invf;
    double s, c;
    sincos(fr, &s, &c);
    g_rcs[i] = (float)c;
    g_rsn[i] = (float)s;
}

__device__ __forceinline__ void transpose_tile(
    const float* __restrict__ src, float* __restrict__ dst, int R, int C,
    int c0, int r0, float (*tile)[33])
{
#pragma unroll
    for (int i = threadIdx.y; i < 32; i += 8)
        tile[i][threadIdx.x] = src[(size_t)(r0 + i) * C + c0 + threadIdx.x];
    __syncthreads();
#pragma unroll
    for (int i = threadIdx.y; i < 32; i += 8)
        dst[(size_t)(c0 + i) * R + r0 + threadIdx.x] =
            __uint_as_float(f2tf(tile[threadIdx.x][i]));
}

// All 4 weight transposes in one launch. grid (64, 64, 4).
__global__ void prep_weights_kernel(const float* __restrict__ Wq, const float* __restrict__ Wk,
                                    const float* __restrict__ Wv, const float* __restrict__ Wo)
{
    __shared__ float tile[32][33];
    int z = blockIdx.z;
    const float* src; float* dst; int R, C;
    if (z == 0)      { src = Wq; dst = g_wqT; R = CC;   C = QDIM; }
    else if (z == 1) { src = Wk; dst = g_wkT; R = CC;   C = KVDIM; }
    else if (z == 2) { src = Wv; dst = g_wvT; R = CC;   C = KVDIM; }
    else             { src = Wo; dst = g_woT; R = QDIM; C = CC; }
    int c0 = blockIdx.x * 32, r0 = blockIdx.y * 32;
    if (c0 >= C || r0 >= R) return;
    transpose_tile(src, dst, R, C, c0, r0, tile);
}

__global__ void transpose_round_kernel(const float* __restrict__ src, float* __restrict__ dst,
                                       int R, int C)
{
    __shared__ float tile[32][33];
    transpose_tile(src, dst, R, C, blockIdx.x * 32, blockIdx.y * 32, tile);
}

// ---------------------------------------------------------------------------
// tf32 GEMM: C[M,N] = A[m][k] @ Bt[n][k]^T, pre-rounded tf32 operands.
// 128x256 block tile, BK=32, 512 threads = 16 warps (warp tile 32x64),
// ldmatrix fragments, 3-stage cp.async, 1 CTA/SM (full regfile: 512x128).
// ---------------------------------------------------------------------------
#define GST 36
#define A_SZ (128 * GST)
#define B_SZ (256 * GST)
#define STAGE_F (A_SZ + B_SZ)
#define GEMM_SMEM (3 * STAGE_F * 4)      // 165.9 KB

__device__ __forceinline__ void gemm_512(
    const float* __restrict__ A, const float* __restrict__ Bt, float* __restrict__ Cm,
    int N, int K, int bm, int bn, float* sm)
{
    int tid = threadIdx.x;
    int lane = tid & 31, wid = tid >> 5;      // 16 warps
    int g = lane >> 2, t = lane & 3;
    int wm = wid & 3, wn = wid >> 2;          // 4 row groups x 4 col groups (64 wide)
    int sel = lane >> 3, r = lane & 7;

    unsigned sbase = (unsigned)__cvta_generic_to_shared(sm);
    unsigned aoff[2], boff[4];
#pragma unroll
    for (int i = 0; i < 2; i++)
        aoff[i] = ((32 * wm + 16 * i + (sel & 1) * 8 + r) * GST + (sel >> 1) * 4) * 4;
#pragma unroll
    for (int jp = 0; jp < 4; jp++)
        boff[jp] = (A_SZ + (64 * wn + 16 * jp + (sel >> 1) * 8 + r) * GST
                    + (sel & 1) * 4) * 4;

    float acc[2][8][4];
#pragma unroll
    for (int i = 0; i < 2; i++)
#pragma unroll
        for (int j = 0; j < 8; j++)
#pragma unroll
            for (int c = 0; c < 4; c++) acc[i][j][c] = 0.f;

    int m8 = tid >> 3, kc = (tid & 7) * 4;    // m8: 0..63
    const float* Ab = A + (size_t)(bm + m8) * K + kc;
    const float* Bb = Bt + (size_t)(bn + m8) * K + kc;
    int nt = K >> 5;

    // prologue: stages 0,1
#pragma unroll
    for (int s = 0; s < 2; s++) {
        float* Sa = sm + s * STAGE_F;
        float* Sb = Sa + A_SZ;
#pragma unroll
        for (int v = 0; v < 2; v++)
            cp16(Sa + (m8 + 64 * v) * GST + kc, Ab + (size_t)(64 * v) * K + s * 32);
#pragma unroll
        for (int v = 0; v < 4; v++)
            cp16(Sb + (m8 + 64 * v) * GST + kc, Bb + (size_t)(64 * v) * K + s * 32);
        CP_COMMIT();
    }

    for (int kt = 0; kt < nt; kt++) {
        CP_WAIT1();
        __syncthreads();

        if (kt + 2 < nt) {
            int s = (kt + 2) % 3;
            float* Sa = sm + s * STAGE_F;
            float* Sb = Sa + A_SZ;
            int ko = (kt + 2) * 32;
#pragma unroll
            for (int v = 0; v < 2; v++)
                cp16(Sa + (m8 + 64 * v) * GST + kc, Ab + (size_t)(64 * v) * K + ko);
#pragma unroll
            for (int v = 0; v < 4; v++)
                cp16(Sb + (m8 + 64 * v) * GST + kc, Bb + (size_t)(64 * v) * K + ko);
        }
        CP_COMMIT();

        unsigned st = sbase + (kt % 3) * (STAGE_F * 4);
#pragma unroll
        for (int ks = 0; ks < 4; ks++) {
            unsigned kb = ks * 32;
            unsigned a[2][4];
#pragma unroll
            for (int i = 0; i < 2; i++)
                ldsm4(a[i][0], a[i][1], a[i][2], a[i][3], st + aoff[i] + kb);
#pragma unroll
            for (int jp = 0; jp < 4; jp++) {
                unsigned b0, b1, b2, b3;
                ldsm4(b0, b1, b2, b3, st + boff[jp] + kb);
                unsigned bl[2] = {b0, b1}, bh[2] = {b2, b3};
#pragma unroll
                for (int i = 0; i < 2; i++) {
                    mma_tf32(acc[i][2 * jp], a[i], bl);
                    mma_tf32(acc[i][2 * jp + 1], a[i], bh);
                }
            }
        }
    }

#pragma unroll
    for (int i = 0; i < 2; i++) {
        int row = bm + 32 * wm + 16 * i + g;
#pragma unroll
        for (int j = 0; j < 8; j++) {
            int col = bn + 64 * wn + 8 * j + 2 * t;
            *(float2*)&Cm[(size_t)row * N + col]       = make_float2(acc[i][j][0], acc[i][j][1]);
            *(float2*)&Cm[(size_t)(row + 8) * N + col] = make_float2(acc[i][j][2], acc[i][j][3]);
        }
    }
}

// qkv: grid (12, 16). x: 0..7 Q (256-col blocks), 8..9 K, 10..11 V.
__global__ __launch_bounds__(512, 1) void qkv_gemm_kernel()
{
    extern __shared__ float sm[];
    int bnb = blockIdx.x;
    int bm  = blockIdx.y * 128;
    const float* B; float* O; int N; int bn;
    if (bnb < 8)       { B = g_wqT; O = g_q; N = QDIM;  bn = bnb * 256; }
    else if (bnb < 10) { B = g_wkT; O = g_k; N = KVDIM; bn = (bnb - 8) * 256; }
    else               { B = g_wvT; O = g_v; N = KVDIM; bn = (bnb - 10) * 256; }
    gemm_512(g_rx, B, O, N, CC, bm, bn, sm);
}

__global__ __launch_bounds__(512, 1) void out_gemm_kernel(float* __restrict__ out)
{
    extern __shared__ float sm[];
    gemm_512(g_y, g_woT, out, CC, QDIM, blockIdx.y * 128, blockIdx.x * 256, sm);
}

// ---------------------------------------------------------------------------
// RoPE: reads precomputed cos/sin table; q plain fp32, k tf32-rounded.
// ---------------------------------------------------------------------------
__global__ void rope_kernel()
{
    __shared__ float cs[64], sn[64];
    int t = blockIdx.x;
    if (threadIdx.x < 64) {
        cs[threadIdx.x] = g_rcs[t * 64 + threadIdx.x];
        sn[threadIdx.x] = g_rsn[t * 64 + threadIdx.x];
    }
    __syncthreads();
    for (int w = threadIdx.x; w < 20 * 64; w += blockDim.x) {
        int hs = w >> 6, p = w & 63;
        float cf = cs[p], sf = sn[p];
        if (hs < NH) {
            float* base = g_q + (size_t)t * QDIM + hs * HD;
            float a = base[p], b = base[p + 64];
            base[p]      = a * cf - b * sf;
            base[p + 64] = b * cf + a * sf;
        } else {
            float* base = g_k + (size_t)t * KVDIM + (hs - NH) * HD;
            float a = base[p], b = base[p + 64];
            base[p]      = __uint_as_float(f2tf(a * cf - b * sf));
            base[p + 64] = __uint_as_float(f2tf(b * cf + a * sf));
        }
    }
}

// ---------------------------------------------------------------------------
// Flash attention (unchanged from measured-best R12): warp tile 16x64,
// ldmatrix fragments, fixed-max softmax, deferred l-reduce.
// ---------------------------------------------------------------------------
#define QS_ST 132
#define KS_ST 132
#define VS_ST 68
#define PS_ST 68
#define VBUF  (128 * VS_ST)
#define ATTN_SMEM ((128 * QS_ST + 64 * KS_ST + 2 * VBUF + 128 * PS_ST) * 4)

__global__ __launch_bounds__(256, 1) void attn_kernel()
{
    extern __shared__ float sh[];
    float* Qs = sh;                      // [128][132] tf32 bits, pre-scaled
    float* Ks = Qs + 128 * QS_ST;        // [64 key][132] tf32 bits
    float* Vb = Ks + 64 * KS_ST;         // 2 x [128 d][68 key] tf32 bits
    float* Ps = Vb + 2 * VBUF;           // [128][68] tf32 bits
    unsigned* Pu = (unsigned*)Ps;

    int qb = 15 - blockIdx.x;
    int h  = blockIdx.y;
    int i0 = qb * 128;
    int kvh = h >> 2;
    int tid = threadIdx.x;
    int lane = tid & 31, wid = tid >> 5;
    int g = lane >> 2, t = lane & 3;
    int sel = lane >> 3, r = lane & 7;
    const float SCALE = 0.08838834764831845f;

    unsigned q_u  = (unsigned)__cvta_generic_to_shared(Qs);
    unsigned k_u  = (unsigned)__cvta_generic_to_shared(Ks);
    unsigned v_u  = (unsigned)__cvta_generic_to_shared(Vb);
    unsigned p_u  = (unsigned)__cvta_generic_to_shared(Ps);
    unsigned qa_off = ((16 * wid + (sel & 1) * 8 + r) * QS_ST + (sel >> 1) * 4) * 4;
    unsigned pa_off = ((16 * wid + (sel & 1) * 8 + r) * PS_ST + (sel >> 1) * 4) * 4;
    unsigned kb_off[4], vb_off[8];
#pragma unroll
    for (int jp = 0; jp < 4; jp++)
        kb_off[jp] = ((16 * jp + (sel >> 1) * 8 + r) * KS_ST + (sel & 1) * 4) * 4;
#pragma unroll
    for (int jp = 0; jp < 8; jp++)
        vb_off[jp] = ((16 * jp + (sel >> 1) * 8 + r) * VS_ST + (sel & 1) * 4) * 4;

    // prefetch K0 and V0
    {
        const float* kp = g_k + kvh * HD;
#pragma unroll
        for (int it = 0; it < 8; it++) {
            int c = it * 256 + tid;
            int row = c >> 5, c4 = (c & 31) * 4;
            cp16(Ks + row * KS_ST + c4, kp + (size_t)row * KVDIM + c4);
        }
        const float* vp = g_vT + (size_t)kvh * HD * TT;
#pragma unroll
        for (int it = 0; it < 8; it++) {
            int c = it * 256 + tid;
            int d = c >> 4, ck = (c & 15) * 4;
            cp16(Vb + d * VS_ST + ck, vp + (size_t)d * TT + ck);
        }
    }
    CP_COMMIT();

    // load Q (scaled + tf32)
#pragma unroll
    for (int v = 0; v < 16; v++) {
        int row = 8 * v + wid;
        float4 q = *(const float4*)&g_q[(size_t)(i0 + row) * QDIM + h * HD + lane * 4];
        q.x *= SCALE; q.y *= SCALE; q.z *= SCALE; q.w *= SCALE;
        *(float4*)&Qs[row * QS_ST + lane * 4] = cvt4(q);
    }

    float l0 = 0.f, l1 = 0.f;
    float oacc[16][4];
#pragma unroll
    for (int j = 0; j < 16; j++)
#pragma unroll
        for (int c = 0; c < 4; c++) oacc[j][c] = 0.f;

    int prow = (16 * wid + g) * PS_ST;
    int nkb = (i0 + 128) >> 6;
    for (int kb = 0; kb < nkb; kb++) {
        int cur = kb & 1;
        unsigned vcur_u = v_u + cur * (VBUF * 4);

        CP_WAIT0();
        __syncthreads();                  // K(kb), V(kb) resident

        if (kb + 1 < nkb) {               // prefetch V(kb+1)
            const float* vpn = g_vT + (size_t)kvh * HD * TT + (kb + 1) * 64;
            float* Vn = Vb + (1 - cur) * VBUF;
#pragma unroll
            for (int it = 0; it < 8; it++) {
                int c = it * 256 + tid;
                int d = c >> 4, ck = (c & 15) * 4;
                cp16(Vn + d * VS_ST + ck, vpn + (size_t)d * TT + ck);
            }
            CP_COMMIT();
        }

        // ---- S = Q @ K^T ----
        float sacc[8][4];
#pragma unroll
        for (int j = 0; j < 8; j++)
#pragma unroll
            for (int c = 0; c < 4; c++) sacc[j][c] = 0.f;

#pragma unroll
        for (int ks = 0; ks < 16; ks++) {
            unsigned kbb = ks * 32;
            unsigned a[4];
            ldsm4(a[0], a[1], a[2], a[3], q_u + qa_off + kbb);
#pragma unroll
            for (int jp = 0; jp < 4; jp++) {
                unsigned b0, b1, b2, b3;
                ldsm4(b0, b1, b2, b3, k_u + kb_off[jp] + kbb);
                unsigned bl[2] = {b0, b1}, bh[2] = {b2, b3};
                mma_tf32(sacc[2 * jp], a, bl);
                mma_tf32(sacc[2 * jp + 1], a, bh);
            }
        }

        __syncthreads();                  // all warps done reading Ks

        if (kb + 1 < nkb) {               // refill K(kb+1); hides under softmax+PV
            const float* kpn = g_k + (size_t)(kb + 1) * 64 * KVDIM + kvh * HD;
#pragma unroll
            for (int it = 0; it < 8; it++) {
                int c = it * 256 + tid;
                int row = c >> 5, c4 = (c & 31) * 4;
                cp16(Ks + row * KS_ST + c4, kpn + (size_t)row * KVDIM + c4);
            }
            CP_COMMIT();
        }

        int j0 = kb * 64;
        if (j0 + 63 > i0) {               // diagonal tile mask (expf(-1e30) == 0)
            int r0 = i0 + 16 * wid + g;
            int r1 = r0 + 8;
#pragma unroll
            for (int j = 0; j < 8; j++) {
                int c = j0 + 8 * j + 2 * t;
                if (c > r0)     sacc[j][0] = -1e30f;
                if (c + 1 > r0) sacc[j][1] = -1e30f;
                if (c > r1)     sacc[j][2] = -1e30f;
                if (c + 1 > r1) sacc[j][3] = -1e30f;
            }
        }

        // exp + per-lane partial sums + write P
#pragma unroll
        for (int j = 0; j < 8; j++) {
            float e0 = __expf(sacc[j][0]);
            float e1 = __expf(sacc[j][1]);
            float e2 = __expf(sacc[j][2]);
            float e3 = __expf(sacc[j][3]);
            l0 += e0 + e1;
            l1 += e2 + e3;
            int pc = 8 * j + 2 * t;
            Pu[prow + pc]                 = f2tf(e0);
            Pu[prow + pc + 1]             = f2tf(e1);
            Pu[prow + 8 * PS_ST + pc]     = f2tf(e2);
            Pu[prow + 8 * PS_ST + pc + 1] = f2tf(e3);
        }
        __syncwarp();

        // ---- O += P @ V ----
#pragma unroll
        for (int ks = 0; ks < 8; ks++) {
            unsigned kbb = ks * 32;
            unsigned a[4];
            ldsm4(a[0], a[1], a[2], a[3], p_u + pa_off + kbb);
#pragma unroll
            for (int jp = 0; jp < 8; jp++) {
                unsigned b0, b1, b2, b3;
                ldsm4(b0, b1, b2, b3, vcur_u + vb_off[jp] + kbb);
                unsigned bl[2] = {b0, b1}, bh[2] = {b2, b3};
                mma_tf32(oacc[2 * jp], a, bl);
                mma_tf32(oacc[2 * jp + 1], a, bh);
            }
        }
    }

    // epilogue: reduce l once, normalize, round tf32
    l0 += __shfl_xor_sync(0xffffffffu, l0, 1);
    l0 += __shfl_xor_sync(0xffffffffu, l0, 2);
    l1 += __shfl_xor_sync(0xffffffffu, l1, 1);
    l1 += __shfl_xor_sync(0xffffffffu, l1, 2);
    float inv0 = 1.f / l0, inv1 = 1.f / l1;
    int row = i0 + 16 * wid + g;
#pragma unroll
    for (int j = 0; j < 16; j++) {
        int col = h * HD + 8 * j + 2 * t;
        float2 c0 = make_float2(__uint_as_float(f2tf(oacc[j][0] * inv0)),
                                __uint_as_float(f2tf(oacc[j][1] * inv0)));
        float2 c1 = make_float2(__uint_as_float(f2tf(oacc[j][2] * inv1)),
                                __uint_as_float(f2tf(oacc[j][3] * inv1)));
        *(float2*)&g_y[(size_t)row * QDIM + col]       = c0;
        *(float2*)&g_y[(size_t)(row + 8) * QDIM + col] = c1;
    }
}

// ---------------------------------------------------------------------------
extern "C" void kernel_launch(void* const* d_in, const int* in_sizes, int n_in,
                              void* d_out, int out_size)
{
    (void)in_sizes; (void)n_in; (void)out_size;
    const float* x  = (const float*)d_in[0];
    const float* Wq = (const float*)d_in[1];
    const float* Wk = (const float*)d_in[2];
    const float* Wv = (const float*)d_in[3];
    const float* Wo = (const float*)d_in[4];
    const int*  pos = (const int*)d_in[5];
    float* out = (float*)d_out;

    cudaFuncSetAttribute(attn_kernel,
                         cudaFuncAttributeMaxDynamicSharedMemorySize, ATTN_SMEM);
    cudaFuncSetAttribute(qkv_gemm_kernel,
                         cudaFuncAttributeMaxDynamicSharedMemorySize, GEMM_SMEM);
    cudaFuncSetAttribute(out_gemm_kernel,
                         cudaFuncAttributeMaxDynamicSharedMemorySize, GEMM_SMEM);

    float* rx = nullptr; float* gv = nullptr; float* gvT = nullptr;
    cudaGetSymbolAddress((void**)&rx,  g_rx);
    cudaGetSymbolAddress((void**)&gv,  g_v);
    cudaGetSymbolAddress((void**)&gvT, g_vT);

    round_copy_kernel<<<TT * CC / 1024, 256>>>(x, rx);
    rope_table_kernel<<<TT * 64 / 256, 256>>>(pos);
    prep_weights_kernel<<<dim3(64, 64, 4), dim3(32, 8)>>>(Wq, Wk, Wv, Wo);

    qkv_gemm_kernel<<<dim3(12, 16), 512, GEMM_SMEM>>>();
    rope_kernel<<<TT, 256>>>();
    transpose_round_kernel<<<dim3(KVDIM / 32, TT / 32), dim3(32, 8)>>>(gv, gvT, TT, KVDIM);
    attn_kernel<<<dim3(16, NH), 256, ATTN_SMEM>>>();
    out_gemm_kernel<<<dim3(8, 16), 512, GEMM_SMEM>>>(out);
}